// round 15
// baseline (speedup 1.0000x reference)
#include <cuda_runtime.h>
#include <cuda_bf16.h>
#include <cstdint>

// ODELinear via mma.sync (HMMA bf16 hi/lo 3-term split, fp32 accum).
// One CTA per trajectory pair (M=128 rows), 96 CTAs, 512 threads.
// Warp pair (w, w+8) shares row-stripe w&7 and splits the n-dimension:
// w handles GEMM1 kc2 0..3 / GEMM2 nc2 0..3, w+8 the 4..7 halves.
// A and A2 operand fragments live in smem (conflict-free 512B/warp blocks);
// per-thread persistent state is only y/P/Q for 4 owned n-chunks -> ~110 regs,
// 4 warps/SMSP for latency hiding.

#define Lg 96
#define Hh 8
#define NT 512

struct __align__(16) Smem {
    uint4 W1F[4][16][32];   // [kc][nc][lane]  = {b0h,b1h,b0l,b1l}
    uint4 W2F[8][8][32];    // [kc2][nc2][lane]
    uint4 A2h[8][8][32];    // [stripe][kc2][lane]  H fragments (hi)
    uint4 A2l[8][8][32];    //                       (lo)
    uint4 Axh[8][4][32];    // [stripe][kc][lane]   stage-input fragments (hi)
    uint4 Axl[8][4][32];    //                       (lo)
    float Ts[Lg];
    float b1s[128];
    float b2s[64];
};

__device__ __forceinline__ uint32_t packbf(float a, float b) {  // lo=a, hi=b
    uint32_t r;
    asm("cvt.rn.bf16x2.f32 %0, %1, %2;" : "=r"(r) : "f"(b), "f"(a));
    return r;
}
__device__ __forceinline__ void split2(float a, float b, uint32_t& hi, uint32_t& lo) {
    hi = packbf(a, b);
    float fa = __uint_as_float(hi << 16);
    float fb = __uint_as_float(hi & 0xFFFF0000u);
    lo = packbf(a - fa, b - fb);
}
__device__ __forceinline__ float tanh_fast(float x) {
    // 1 - 2/(e^{2x}+1): exact at saturation, rel err ~1e-6
    float e = __expf(2.0f * x);
    return 1.0f - __fdividef(2.0f, e + 1.0f);
}

#define MMA(d, a, b0, b1)                                                     \
    asm volatile(                                                             \
        "mma.sync.aligned.m16n8k16.row.col.f32.bf16.bf16.f32 "                \
        "{%0,%1,%2,%3},{%4,%5,%6,%7},{%8,%9},{%0,%1,%2,%3};"                  \
        : "+f"((d)[0]), "+f"((d)[1]), "+f"((d)[2]), "+f"((d)[3])              \
        : "r"((a)[0]), "r"((a)[1]), "r"((a)[2]), "r"((a)[3]), "r"(b0), "r"(b1))

__global__ void __launch_bounds__(NT, 1)
ode_kernel(const float* __restrict__ x, const float* __restrict__ Tg,
           const float* __restrict__ W1g, const float* __restrict__ b1g,
           const float* __restrict__ W2g, const float* __restrict__ b2g,
           float* __restrict__ out) {
    extern __shared__ __align__(16) char smraw[];
    Smem* s = (Smem*)smraw;
    const int tid = threadIdx.x;
    const int lane = tid & 31;
    const int w = tid >> 5;
    const int stripe = w & 7;   // row-stripe: rows 16*stripe .. +15
    const int nhalf = w >> 3;   // n-dimension half
    const int base4 = nhalf * 4;
    const int gr = lane >> 2;   // fragment group row 0..7
    const int tg = lane & 3;    // thread-in-group 0..3
    const int pi = blockIdx.x;
    const int trajF = pi, trajB = 95 - pi;
    const int len = 95 - pi;

    // ---- weight fragment prep (once) ----
    for (int idx = tid; idx < 2048; idx += NT) {
        int ln = idx & 31, nc = (idx >> 5) & 15, kc = idx >> 9;
        int g2 = ln >> 2, t2 = ln & 3;
        int k0 = kc * 16 + t2 * 2, nn = nc * 8 + g2;
        float w00 = W1g[k0 * 128 + nn], w01 = W1g[(k0 + 1) * 128 + nn];
        float w10 = W1g[(k0 + 8) * 128 + nn], w11 = W1g[(k0 + 9) * 128 + nn];
        uint32_t h0, l0, h1, l1;
        split2(w00, w01, h0, l0);
        split2(w10, w11, h1, l1);
        s->W1F[kc][nc][ln] = make_uint4(h0, h1, l0, l1);
    }
    for (int idx = tid; idx < 2048; idx += NT) {
        int ln = idx & 31, nc = (idx >> 5) & 7, kc = idx >> 8;
        int g2 = ln >> 2, t2 = ln & 3;
        int k0 = kc * 16 + t2 * 2, nn = nc * 8 + g2;
        float w00 = W2g[k0 * 64 + nn], w01 = W2g[(k0 + 1) * 64 + nn];
        float w10 = W2g[(k0 + 8) * 64 + nn], w11 = W2g[(k0 + 9) * 64 + nn];
        uint32_t h0, l0, h1, l1;
        split2(w00, w01, h0, l0);
        split2(w10, w11, h1, l1);
        s->W2F[kc][nc][ln] = make_uint4(h0, h1, l0, l1);
    }
    if (tid < 128) s->b1s[tid] = b1g[tid];
    if (tid < 64) s->b2s[tid] = b2g[tid];
    if (tid < Lg) s->Ts[tid] = Tg[tid];

    // ---- per-thread rows: ra = 16*stripe+gr, rb = ra+8 ----
    const bool fwd = (stripe < 4);
    const int traj = fwd ? trajF : trajB;
    const int ra = stripe * 16 + gr;
    const int ga = ra & 63, gb = ga + 8;
    const int bA = ga >> 3, hA = ga & 7;
    const int bB = gb >> 3, hB = gb & 7;
    const float* pA = x + (((bA * Lg + traj) * Hh + hA) << 6);
    const float* pB = x + (((bB * Lg + traj) * Hh + hB) << 6);

    // persistent state: own 4 n-chunks (nc2 = base4+local), rows {gr, gr+8}
    float yt[4][4], Pt[4][4], Qt[4][4];
#pragma unroll
    for (int local = 0; local < 4; ++local) {
        int c = (base4 + local) * 8 + tg * 2;
        float2 va = *(const float2*)(pA + c);
        float2 vb = *(const float2*)(pB + c);
        yt[local][0] = va.x; yt[local][1] = va.y;
        yt[local][2] = vb.x; yt[local][3] = vb.y;
    }

    // initial stage-input fragments (own 2 kc) -> smem
#pragma unroll
    for (int p = 0; p < 2; ++p) {
        int kc = nhalf * 2 + p;
        uint32_t h[4], l[4];
        split2(yt[2 * p][0], yt[2 * p][1], h[0], l[0]);
        split2(yt[2 * p][2], yt[2 * p][3], h[1], l[1]);
        split2(yt[2 * p + 1][0], yt[2 * p + 1][1], h[2], l[2]);
        split2(yt[2 * p + 1][2], yt[2 * p + 1][3], h[3], l[3]);
        s->Axh[stripe][kc][lane] = make_uint4(h[0], h[1], h[2], h[3]);
        s->Axl[stripe][kc][lane] = make_uint4(l[0], l[1], l[2], l[3]);
    }

    // output bases (float indices); element (b,i,j,h,e,2)
    float* obA = out + (size_t)(bA * Lg + traj) * 98304 + hA * 128 + tg * 4;
    float* obB = out + (size_t)(bB * Lg + traj) * 98304 + hB * 128 + tg * 4;

    __syncthreads();  // weights + initial fragments ready

    // diagonal emission j == trajF (fwd stripes; each warp its own n-cols)
    if (fwd) {
#pragma unroll
        for (int local = 0; local < 4; ++local) {
            int nc2 = base4 + local;
            *(float4*)(obA + (size_t)trajF * 1024 + nc2 * 16) =
                make_float4(yt[local][0], yt[local][0], yt[local][1], yt[local][1]);
            *(float4*)(obB + (size_t)trajF * 1024 + nc2 * 16) =
                make_float4(yt[local][2], yt[local][2], yt[local][3], yt[local][3]);
        }
    }

    const float* Ts = s->Ts;
    for (int n = 0; n < len; ++n) {
        const float dt = fwd ? (Ts[pi + n + 1] - Ts[pi + n])
                             : (Ts[94 - pi - n] - Ts[95 - pi - n]);  // negative
        const int j = fwd ? (pi + n + 1) : (94 - pi - n);

#pragma unroll 1
        for (int m = 0; m < 4; ++m) {
            // ---- GEMM1: own 4 A2 k-chunks; operands streamed from smem ----
#pragma unroll 1
            for (int t = 0; t < 4; ++t) {
                const int kc2 = base4 + t;
                float acc[2][4] = {{0, 0, 0, 0}, {0, 0, 0, 0}};
#pragma unroll
                for (int kc = 0; kc < 4; ++kc) {
                    uint4 ahv = s->Axh[stripe][kc][lane];
                    uint4 alv = s->Axl[stripe][kc][lane];
                    uint32_t* ah = (uint32_t*)&ahv;
                    uint32_t* al = (uint32_t*)&alv;
                    uint4 wv0 = s->W1F[kc][2 * kc2][lane];
                    uint4 wv1 = s->W1F[kc][2 * kc2 + 1][lane];
                    MMA(acc[0], ah, wv0.x, wv0.y);
                    MMA(acc[0], ah, wv0.z, wv0.w);
                    MMA(acc[0], al, wv0.x, wv0.y);
                    MMA(acc[1], ah, wv1.x, wv1.y);
                    MMA(acc[1], ah, wv1.z, wv1.w);
                    MMA(acc[1], al, wv1.x, wv1.y);
                }
                // bias + tanh -> A2 fragment -> smem
                const int cb = kc2 * 16 + tg * 2;
                float2 b1a = *(const float2*)&s->b1s[cb];
                float2 b1b = *(const float2*)&s->b1s[cb + 8];
                uint32_t h[4], l[4];
                split2(tanh_fast(acc[0][0] + b1a.x), tanh_fast(acc[0][1] + b1a.y),
                       h[0], l[0]);
                split2(tanh_fast(acc[0][2] + b1a.x), tanh_fast(acc[0][3] + b1a.y),
                       h[1], l[1]);
                split2(tanh_fast(acc[1][0] + b1b.x), tanh_fast(acc[1][1] + b1b.y),
                       h[2], l[2]);
                split2(tanh_fast(acc[1][2] + b1b.x), tanh_fast(acc[1][3] + b1b.y),
                       h[3], l[3]);
                s->A2h[stripe][kc2][lane] = make_uint4(h[0], h[1], h[2], h[3]);
                s->A2l[stripe][kc2][lane] = make_uint4(l[0], l[1], l[2], l[3]);
            }
            __syncthreads();

            // ---- GEMM2: own 4 n-chunks over all 8 k-chunks ----
            float acc2[4][4] = {{0, 0, 0, 0}, {0, 0, 0, 0}, {0, 0, 0, 0}, {0, 0, 0, 0}};
#pragma unroll 1
            for (int kc2 = 0; kc2 < 8; ++kc2) {
                uint4 a2hv = s->A2h[stripe][kc2][lane];
                uint4 a2lv = s->A2l[stripe][kc2][lane];
                uint32_t* a2h = (uint32_t*)&a2hv;
                uint32_t* a2l = (uint32_t*)&a2lv;
#pragma unroll
                for (int ncl = 0; ncl < 4; ++ncl) {
                    uint4 wv = s->W2F[kc2][base4 + ncl][lane];
                    MMA(acc2[ncl], a2h, wv.x, wv.y);
                    MMA(acc2[ncl], a2h, wv.z, wv.w);
                    MMA(acc2[ncl], a2l, wv.x, wv.y);
                }
            }

            // ---- epilogue: RK4 combine on own n-chunks ----
            float stv[4][4];
#pragma unroll
            for (int local = 0; local < 4; ++local) {
                const int c = (base4 + local) * 8 + tg * 2;
                float2 b2v = *(const float2*)&s->b2s[c];
#pragma unroll
                for (int i = 0; i < 4; ++i) {
                    float kv = acc2[local][i] + ((i & 1) ? b2v.y : b2v.x);
                    if (m == 0) {
                        Pt[local][i] = kv;
                        Qt[local][i] = kv;
                        stv[local][i] = fmaf(dt * (1.0f / 3.0f), kv, yt[local][i]);
                    } else if (m == 1) {
                        stv[local][i] = fmaf(
                            dt, kv, fmaf(-dt * (1.0f / 3.0f), Pt[local][i], yt[local][i]));
                        Qt[local][i] = fmaf(3.0f, kv, Qt[local][i]);
                        Pt[local][i] = Pt[local][i] - kv;
                    } else if (m == 2) {
                        stv[local][i] = fmaf(dt, Pt[local][i] + kv, yt[local][i]);
                        Qt[local][i] = fmaf(3.0f, kv, Qt[local][i]);
                    } else {
                        yt[local][i] = fmaf(dt * 0.125f, Qt[local][i] + kv, yt[local][i]);
                        stv[local][i] = yt[local][i];
                    }
                }
            }
            // rebuild own stage-input fragments -> smem
#pragma unroll
            for (int p = 0; p < 2; ++p) {
                int kc = nhalf * 2 + p;
                uint32_t h[4], l[4];
                split2(stv[2 * p][0], stv[2 * p][1], h[0], l[0]);
                split2(stv[2 * p][2], stv[2 * p][3], h[1], l[1]);
                split2(stv[2 * p + 1][0], stv[2 * p + 1][1], h[2], l[2]);
                split2(stv[2 * p + 1][2], stv[2 * p + 1][3], h[3], l[3]);
                s->Axh[stripe][kc][lane] = make_uint4(h[0], h[1], h[2], h[3]);
                s->Axl[stripe][kc][lane] = make_uint4(l[0], l[1], l[2], l[3]);
            }
            if (m == 3) {  // fused emission; x0 re-read from L2-resident x
#pragma unroll
                for (int local = 0; local < 4; ++local) {
                    int nc2 = base4 + local;
                    int c = nc2 * 8 + tg * 2;
                    float2 xa = *(const float2*)(pA + c);
                    float2 xb = *(const float2*)(pB + c);
                    *(float4*)(obA + (size_t)j * 1024 + nc2 * 16) =
                        make_float4(xa.x, yt[local][0], xa.y, yt[local][1]);
                    *(float4*)(obB + (size_t)j * 1024 + nc2 * 16) =
                        make_float4(xb.x, yt[local][2], xb.y, yt[local][3]);
                }
            }
            __syncthreads();
        }
    }
}

extern "C" void kernel_launch(void* const* d_in, const int* in_sizes, int n_in,
                              void* d_out, int out_size) {
    (void)in_sizes; (void)n_in; (void)out_size;
    cudaFuncSetAttribute(ode_kernel, cudaFuncAttributeMaxDynamicSharedMemorySize,
                         (int)sizeof(Smem));
    ode_kernel<<<96, NT, sizeof(Smem)>>>(
        (const float*)d_in[0], (const float*)d_in[1], (const float*)d_in[2],
        (const float*)d_in[3], (const float*)d_in[4], (const float*)d_in[5],
        (float*)d_out);
}